// round 2
// baseline (speedup 1.0000x reference)
#include <cuda_runtime.h>
#include <math.h>
#include <stdint.h>

#define BB 4
#define C 96
#define H 128
#define W 128
#define HW (H*W)          // 16384
#define KKc 9
#define CK (C*KKc)        // 864
#define NPIX (BB*HW)      // 65536 per channel

// ---------------- device scratch (no allocations allowed) ----------------
__device__ float  g_col [ (size_t)BB * CK * HW ];   // 226.5 MB deform-col
__device__ float  g_w27 [ 27 * CK ];                // concatenated offset|mask weights
__device__ float4 g_wts [ (size_t)BB * KKc * HW ];  // bilinear weights (mask folded)
__device__ int4   g_idx [ (size_t)BB * KKc * HW ];  // bilinear gather indices
__device__ float  g_conv[ (size_t)BB * C * HW ];    // deform-conv output
__device__ float  g_act [ (size_t)BB * C * HW ];    // post BN+leakyrelu
__device__ float  g_stats[ 2 * C ];                 // mean | rstd

// packed f32x2 FMA (FFMA2) — only reachable via explicit PTX on sm_10x
#define FMA2(d, a, b) \
    asm("fma.rn.f32x2 %0, %1, %2, %0;" : "+l"(d) : "l"(a), "l"(b))

__device__ __forceinline__ unsigned long long bcast2(float v) {
    unsigned long long r;
    unsigned int u = __float_as_uint(v);
    asm("mov.b64 %0, {%1, %1};" : "=l"(r) : "r"(u));
    return r;
}

// ---------------- tiny helper ----------------
__global__ void concat27_kernel(const float* __restrict__ offw,
                                const float* __restrict__ modw,
                                float* __restrict__ dst) {
    int i = blockIdx.x * blockDim.x + threadIdx.x;
    if (i >= 27 * CK) return;
    dst[i] = (i < 18 * CK) ? offw[i] : modw[i - 18 * CK];
}

// ---------------------------------------------------------------------------
// Fused offset/mask conv (implicit GEMM, B built from shifted x reads) +
// epilogue that converts raw conv outputs into bilinear weight/index tables.
// One block = one image row (128 pixels) of one batch; computes ALL 27
// channels for those pixels, so the epilogue has everything it needs.
// ---------------------------------------------------------------------------
__global__ void __launch_bounds__(256) offconv_prep_kernel(
    const float* __restrict__ A,      // [27][864]
    const float* __restrict__ X,      // [B][C][H][W]
    const float* __restrict__ off_b,  // [18]
    const float* __restrict__ mod_b,  // [9]
    float4* __restrict__ wts,
    int4*  __restrict__ idx)
{
    constexpr int BK = 18;            // 864 / 18 = 48 iters, = 2 channels/iter
    __shared__ float As[BK][33];      // 32 rows (27 used), padded
    __shared__ float Bs[BK][128];
    __shared__ float Om[27][128];

    int tid = threadIdx.x;
    int b = blockIdx.y;
    int h = blockIdx.x;               // image row (W == 128 == BN)
    int tx = tid & 15;                // 16 col-groups of 8
    int ty = tid >> 4;                // 16 row-groups of 2

    const float* Xb = X + (size_t)b * C * HW;

    unsigned long long acc2[2][4];
    #pragma unroll
    for (int i = 0; i < 2; i++)
        #pragma unroll
        for (int j = 0; j < 4; j++) acc2[i][j] = 0ull;

    for (int k0 = 0; k0 < CK; k0 += BK) {
        // A tile: 32 x 18 (rows 27..31 zeroed)
        for (int e = tid; e < 32 * BK; e += 256) {
            int m = e / BK, k = e - m * BK;
            As[k][m] = (m < 27) ? A[m * CK + k0 + k] : 0.f;
        }
        // implicit B tile: Bs[k][col] = x[c][h+dy][col+dx] (zero-padded)
        #pragma unroll
        for (int i = 0; i < 9; i++) {
            int e = tid + i * 256;
            int k = e >> 7, colw = e & 127;
            int kg = k0 + k;
            int c  = kg / 9;
            int kk = kg - c * 9;
            int yy = h + kk / 3 - 1;
            int xx = colw + (kk % 3) - 1;
            float v = 0.f;
            if (yy >= 0 && yy < H && xx >= 0 && xx < W)
                v = Xb[(size_t)c * HW + yy * W + xx];
            Bs[k][colw] = v;
        }
        __syncthreads();

        #pragma unroll
        for (int k = 0; k < BK; k++) {
            unsigned long long a2[2];
            a2[0] = bcast2(As[k][ty * 2]);
            a2[1] = bcast2(As[k][ty * 2 + 1]);
            const unsigned long long* bp =
                reinterpret_cast<const unsigned long long*>(&Bs[k][tx * 8]);
            unsigned long long b0 = bp[0], b1 = bp[1], b2v = bp[2], b3 = bp[3];
            #pragma unroll
            for (int i = 0; i < 2; i++) {
                FMA2(acc2[i][0], a2[i], b0);
                FMA2(acc2[i][1], a2[i], b1);
                FMA2(acc2[i][2], a2[i], b2v);
                FMA2(acc2[i][3], a2[i], b3);
            }
        }
        __syncthreads();
    }

    // stage raw conv outputs in smem
    #pragma unroll
    for (int i = 0; i < 2; i++) {
        int m = ty * 2 + i;
        if (m < 27) {
            #pragma unroll
            for (int j = 0; j < 4; j++) {
                float2 p = *reinterpret_cast<float2*>(&acc2[i][j]);
                Om[m][tx * 8 + 2 * j]     = p.x;
                Om[m][tx * 8 + 2 * j + 1] = p.y;
            }
        }
    }
    __syncthreads();

    // epilogue: bilinear weight/index tables (bias+sigmoid+mask+validity folded)
    size_t base = ((size_t)b * KKc) * HW + h * W;
    for (int it = tid; it < KKc * 128; it += 256) {
        int kk = it >> 7, colw = it & 127;
        float offy = Om[2 * kk][colw]     + off_b[2 * kk];
        float offx = Om[2 * kk + 1][colw] + off_b[2 * kk + 1];
        float mraw = Om[18 + kk][colw]    + mod_b[kk];
        float mval = 2.f / (1.f + expf(-mraw));

        float py = (float)h    - 1.f + (float)(kk / 3) + offy;
        float px = (float)colw - 1.f + (float)(kk % 3) + offx;
        float y0f = floorf(py), x0f = floorf(px);
        float dy = py - y0f, dx = px - x0f;
        int y0 = (int)y0f, x0 = (int)x0f;
        int y1 = y0 + 1,   x1 = x0 + 1;

        float v00 = (y0 >= 0 && y0 < H && x0 >= 0 && x0 < W) ? 1.f : 0.f;
        float v01 = (y0 >= 0 && y0 < H && x1 >= 0 && x1 < W) ? 1.f : 0.f;
        float v10 = (y1 >= 0 && y1 < H && x0 >= 0 && x0 < W) ? 1.f : 0.f;
        float v11 = (y1 >= 0 && y1 < H && x1 >= 0 && x1 < W) ? 1.f : 0.f;

        int y0c = min(max(y0, 0), H - 1), y1c = min(max(y1, 0), H - 1);
        int x0c = min(max(x0, 0), W - 1), x1c = min(max(x1, 0), W - 1);

        float4 wv;
        wv.x = (1.f - dy) * (1.f - dx) * mval * v00;
        wv.y = (1.f - dy) * dx         * mval * v01;
        wv.z = dy         * (1.f - dx) * mval * v10;
        wv.w = dy         * dx         * mval * v11;
        int4 iv;
        iv.x = y0c * W + x0c;  iv.y = y0c * W + x1c;
        iv.z = y1c * W + x0c;  iv.w = y1c * W + x1c;

        wts[base + (size_t)kk * HW + colw] = wv;
        idx[base + (size_t)kk * HW + colw] = iv;
    }
}

// ---------------- deformable im2col via precomputed tables ----------------
__global__ void deform_col_kernel(const float* __restrict__ in,
                                  const float4* __restrict__ wts,
                                  const int4* __restrict__ idx,
                                  float* __restrict__ col) {
    int t = blockIdx.x * blockDim.x + threadIdx.x;   // (b*9+kk)*HW + hw
    if (t >= BB * KKc * HW) return;
    int hw = t & (HW - 1);
    int u  = t >> 14;
    int kk = u % KKc;
    int b  = u / KKc;

    float4 w = wts[t];
    int4  ii = idx[t];

    const float* p = in + (size_t)b * C * HW;
    float* o = col + ((size_t)b * CK + kk) * HW + hw;
    #pragma unroll 4
    for (int c = 0; c < C; c++) {
        float v = p[ii.x] * w.x + p[ii.y] * w.y + p[ii.z] * w.z + p[ii.w] * w.w;
        *o = v;
        p += HW;
        o += (size_t)KKc * HW;
    }
}

// ---------------- main GEMM: 96 x 864 x 16384/batch, f32x2 packed ----------
__global__ void __launch_bounds__(256) sgemm96_kernel(
    const float* __restrict__ A,      // [96][864]
    const float* __restrict__ Bmat,   // [B][864][HW]
    float* __restrict__ Out)          // [B][96][HW]
{
    constexpr int BK = 16, BN = 128, BM = 96;
    __shared__ float As[BK][BM + 1];
    __shared__ float Bs[BK][BN];

    int tid = threadIdx.x;
    int b   = blockIdx.y;
    int n0  = blockIdx.x * BN;
    int tx  = tid & 15;
    int ty  = tid >> 4;

    const float* Bb = Bmat + (size_t)b * CK * HW;

    unsigned long long acc2[6][4];
    #pragma unroll
    for (int i = 0; i < 6; i++)
        #pragma unroll
        for (int j = 0; j < 4; j++) acc2[i][j] = 0ull;

    int br = tid >> 5;           // 0..7
    int bc = (tid & 31) * 4;     // 0..124

    for (int k0 = 0; k0 < CK; k0 += BK) {
        #pragma unroll
        for (int i = 0; i < (BM * BK) / 256; i++) {
            int e = tid + i * 256;
            int m = e >> 4;
            int k = e & 15;
            As[k][m] = A[m * CK + k0 + k];
        }
        #pragma unroll
        for (int i = 0; i < 2; i++) {
            float4 v = *reinterpret_cast<const float4*>(
                Bb + (size_t)(k0 + br + 8 * i) * HW + n0 + bc);
            *reinterpret_cast<float4*>(&Bs[br + 8 * i][bc]) = v;
        }
        __syncthreads();

        #pragma unroll
        for (int k = 0; k < BK; k++) {
            unsigned long long a2[6];
            #pragma unroll
            for (int i = 0; i < 6; i++) a2[i] = bcast2(As[k][ty * 6 + i]);
            const unsigned long long* bp =
                reinterpret_cast<const unsigned long long*>(&Bs[k][tx * 8]);
            unsigned long long b0 = bp[0], b1 = bp[1], b2v = bp[2], b3 = bp[3];
            #pragma unroll
            for (int i = 0; i < 6; i++) {
                FMA2(acc2[i][0], a2[i], b0);
                FMA2(acc2[i][1], a2[i], b1);
                FMA2(acc2[i][2], a2[i], b2v);
                FMA2(acc2[i][3], a2[i], b3);
            }
        }
        __syncthreads();
    }

    #pragma unroll
    for (int i = 0; i < 6; i++) {
        int m = ty * 6 + i;
        float* op = Out + ((size_t)b * BM + m) * HW + n0 + tx * 8;
        float2 p0 = *reinterpret_cast<float2*>(&acc2[i][0]);
        float2 p1 = *reinterpret_cast<float2*>(&acc2[i][1]);
        float2 p2 = *reinterpret_cast<float2*>(&acc2[i][2]);
        float2 p3 = *reinterpret_cast<float2*>(&acc2[i][3]);
        *reinterpret_cast<float4*>(op)     = make_float4(p0.x, p0.y, p1.x, p1.y);
        *reinterpret_cast<float4*>(op + 4) = make_float4(p2.x, p2.y, p3.x, p3.y);
    }
}

// ---------------- batch norm ----------------
__global__ void bn_stats_kernel(const float* __restrict__ X,
                                float* __restrict__ stats) {
    int c = blockIdx.x;
    float s = 0.f, s2 = 0.f;
    for (int i = threadIdx.x; i < NPIX; i += blockDim.x) {
        int b  = i >> 14;
        int hw = i & (HW - 1);
        float v = X[((size_t)b * C + c) * HW + hw];
        s  += v;
        s2 += v * v;
    }
    __shared__ float sh[256], sh2[256];
    sh[threadIdx.x] = s; sh2[threadIdx.x] = s2;
    __syncthreads();
    for (int st = 128; st > 0; st >>= 1) {
        if (threadIdx.x < st) {
            sh[threadIdx.x]  += sh[threadIdx.x + st];
            sh2[threadIdx.x] += sh2[threadIdx.x + st];
        }
        __syncthreads();
    }
    if (threadIdx.x == 0) {
        float inv = 1.f / (float)NPIX;
        float mean = sh[0] * inv;
        float var  = sh2[0] * inv - mean * mean;
        stats[c]     = mean;
        stats[C + c] = rsqrtf(var + 1e-5f);
    }
}

__global__ void bn_lrelu_kernel(const float* __restrict__ X,
                                const float* __restrict__ gam,
                                const float* __restrict__ bet,
                                const float* __restrict__ stats,
                                float* __restrict__ O) {
    int idx = blockIdx.x * blockDim.x + threadIdx.x;
    if (idx >= BB * C * HW) return;
    int c = (idx / HW) % C;
    float v = (X[idx] - stats[c]) * stats[C + c] * gam[c] + bet[c];
    O[idx] = v >= 0.f ? v : 0.1f * v;
}

__global__ void bn_add_kernel(const float* __restrict__ Xres,
                              const float* __restrict__ Hc,
                              const float* __restrict__ gam,
                              const float* __restrict__ bet,
                              const float* __restrict__ stats,
                              float* __restrict__ O) {
    int idx = blockIdx.x * blockDim.x + threadIdx.x;
    if (idx >= BB * C * HW) return;
    int c = (idx / HW) % C;
    float v = (Hc[idx] - stats[c]) * stats[C + c] * gam[c] + bet[c];
    O[idx] = Xres[idx] + v;
}

// ---------------- launch ----------------
extern "C" void kernel_launch(void* const* d_in, const int* in_sizes, int n_in,
                              void* d_out, int out_size) {
    const float* x        = (const float*)d_in[0];
    const float* d1_off_w = (const float*)d_in[1];
    const float* d1_off_b = (const float*)d_in[2];
    const float* d1_mod_w = (const float*)d_in[3];
    const float* d1_mod_b = (const float*)d_in[4];
    const float* d1_w     = (const float*)d_in[5];
    const float* d2_off_w = (const float*)d_in[6];
    const float* d2_off_b = (const float*)d_in[7];
    const float* d2_mod_w = (const float*)d_in[8];
    const float* d2_mod_b = (const float*)d_in[9];
    const float* d2_w     = (const float*)d_in[10];
    const float* bn_g     = (const float*)d_in[11];
    const float* bn_b     = (const float*)d_in[12];
    float* out = (float*)d_out;

    float *p_col, *p_w27, *p_conv, *p_act, *p_stats;
    float4* p_wts; int4* p_idx;
    cudaGetSymbolAddress((void**)&p_col,   g_col);
    cudaGetSymbolAddress((void**)&p_w27,   g_w27);
    cudaGetSymbolAddress((void**)&p_wts,   g_wts);
    cudaGetSymbolAddress((void**)&p_idx,   g_idx);
    cudaGetSymbolAddress((void**)&p_conv,  g_conv);
    cudaGetSymbolAddress((void**)&p_act,   g_act);
    cudaGetSymbolAddress((void**)&p_stats, g_stats);

    const int NT = 256;
    const int nCol  = BB * KKc * HW;                 // 589824
    const int nElem = BB * C * HW;                   // 6291456
    dim3 gemm_grid(HW / 128, BB);                    // (128, 4)

    // ---------- layer 1 ----------
    concat27_kernel<<<(27 * CK + NT - 1) / NT, NT>>>(d1_off_w, d1_mod_w, p_w27);
    offconv_prep_kernel<<<gemm_grid, NT>>>(p_w27, x, d1_off_b, d1_mod_b, p_wts, p_idx);
    deform_col_kernel<<<(nCol + NT - 1) / NT, NT>>>(x, p_wts, p_idx, p_col);
    sgemm96_kernel<<<gemm_grid, NT>>>(d1_w, p_col, p_conv);
    bn_stats_kernel<<<C, NT>>>(p_conv, p_stats);
    bn_lrelu_kernel<<<(nElem + NT - 1) / NT, NT>>>(p_conv, bn_g, bn_b, p_stats, p_act);

    // ---------- layer 2 ----------
    concat27_kernel<<<(27 * CK + NT - 1) / NT, NT>>>(d2_off_w, d2_mod_w, p_w27);
    offconv_prep_kernel<<<gemm_grid, NT>>>(p_w27, p_act, d2_off_b, d2_mod_b, p_wts, p_idx);
    deform_col_kernel<<<(nCol + NT - 1) / NT, NT>>>(p_act, p_wts, p_idx, p_col);
    sgemm96_kernel<<<gemm_grid, NT>>>(d2_w, p_col, p_conv);
    bn_stats_kernel<<<C, NT>>>(p_conv, p_stats);
    bn_add_kernel<<<(nElem + NT - 1) / NT, NT>>>(x, p_conv, bn_g, bn_b, p_stats, out);
}

// round 3
// speedup vs baseline: 1.3245x; 1.3245x over previous
#include <cuda_runtime.h>
#include <math.h>
#include <stdint.h>

#define BB 4
#define C 96
#define H 128
#define W 128
#define HW (H*W)          // 16384
#define KKc 9
#define CK (C*KKc)        // 864
#define NPIX (BB*HW)      // 65536 per channel

typedef unsigned long long ull;

// ---------------- device scratch (no allocations allowed) ----------------
__device__ float  g_col [ (size_t)BB * CK * HW ];   // 226.5 MB deform-col
__device__ ull    g_wtp [ CK * 14 ];                // offset|mask weights, opair-packed
__device__ float4 g_wts [ (size_t)BB * KKc * HW ];  // bilinear weights (mask folded)
__device__ int4   g_idx [ (size_t)BB * KKc * HW ];  // bilinear gather indices
__device__ float  g_conv[ (size_t)BB * C * HW ];    // deform-conv output
__device__ float  g_act [ (size_t)BB * C * HW ];    // post BN+leakyrelu
__device__ float  g_stats[ 2 * C ];                 // mean | rstd

// packed f32x2 FMA (FFMA2) — only reachable via explicit PTX on sm_10x
#define FMA2(d, a, b) \
    asm("fma.rn.f32x2 %0, %1, %2, %0;" : "+l"(d) : "l"(a), "l"(b))

__device__ __forceinline__ ull bcast2(float v) {
    ull r;
    unsigned int u = __float_as_uint(v);
    asm("mov.b64 %0, {%1, %1};" : "=l"(r) : "r"(u));
    return r;
}

// ---------------- weight prep: wtp[ck][j] = (w[2j][ck], w[2j+1][ck]) --------
// w[o] = off_w[o] for o<18, mod_w[o-18] for 18<=o<27, 0 for o=27 (pad)
__global__ void wprep_kernel(const float* __restrict__ offw,
                             const float* __restrict__ modw,
                             ull* __restrict__ wtp) {
    int t = blockIdx.x * blockDim.x + threadIdx.x;   // ck*14 + j
    if (t >= CK * 14) return;
    int ck = t / 14, j = t - ck * 14;
    int o0 = 2 * j, o1 = 2 * j + 1;
    float a = (o0 < 18) ? offw[o0 * CK + ck] : modw[(o0 - 18) * CK + ck];
    float b = 0.f;
    if (o1 < 27)
        b = (o1 < 18) ? offw[o1 * CK + ck] : modw[(o1 - 18) * CK + ck];
    float2 p = make_float2(a, b);
    wtp[t] = *reinterpret_cast<ull*>(&p);
}

// ---------------------------------------------------------------------------
// Direct 3x3 conv producing 27 outputs per pixel, fused with the bilinear
// table epilogue. Outputs packed pairwise in f32x2 accumulators.
// Block: 64 threads = 64 pixel-columns x 2 output rows.
// grid.x encodes (row-pair, column-half); grid.y = batch.
// ---------------------------------------------------------------------------
__global__ void __launch_bounds__(64) offconv_kernel(
    const ull* __restrict__ wtp,     // [864][14] packed pairs
    const float* __restrict__ X,     // [B][C][H][W]
    const float* __restrict__ off_b, // [18]
    const float* __restrict__ mod_b, // [9]
    float4* __restrict__ wts,
    int4*  __restrict__ idx)
{
    int half = blockIdx.x & 1;
    int h0   = (blockIdx.x >> 1) * 2;
    int b    = blockIdx.y;
    int pix  = half * 64 + threadIdx.x;

    const float* Xb = X + (size_t)b * C * HW;

    ull acc[2][14];
    #pragma unroll
    for (int r = 0; r < 2; r++)
        #pragma unroll
        for (int j = 0; j < 14; j++) acc[r][j] = 0ull;

    bool xm_ok = (pix > 0);
    bool xp_ok = (pix < W - 1);

    for (int c = 0; c < C; c++) {
        // 12 taps: rows h0-1..h0+2, cols pix-1..pix+1 (zero padded), broadcast-packed
        ull tb[4][3];
        #pragma unroll
        for (int rr = 0; rr < 4; rr++) {
            int y = h0 - 1 + rr;
            bool yok = (y >= 0) && (y < H);
            const float* row = Xb + (size_t)c * HW + y * W + pix;
            float vm = (yok && xm_ok) ? row[-1] : 0.f;
            float v0 = yok ? row[0] : 0.f;
            float vp = (yok && xp_ok) ? row[1] : 0.f;
            tb[rr][0] = bcast2(vm);
            tb[rr][1] = bcast2(v0);
            tb[rr][2] = bcast2(vp);
        }
        const ulonglong2* wrow =
            reinterpret_cast<const ulonglong2*>(wtp + (size_t)c * 9 * 14);
        #pragma unroll
        for (int ky = 0; ky < 3; ky++) {
            #pragma unroll
            for (int kx = 0; kx < 3; kx++) {
                int tap = ky * 3 + kx;
                ull t0 = tb[ky][kx];
                ull t1 = tb[ky + 1][kx];
                #pragma unroll
                for (int j2 = 0; j2 < 7; j2++) {
                    ulonglong2 wv = wrow[tap * 7 + j2];
                    FMA2(acc[0][2 * j2],     wv.x, t0);
                    FMA2(acc[1][2 * j2],     wv.x, t1);
                    FMA2(acc[0][2 * j2 + 1], wv.y, t0);
                    FMA2(acc[1][2 * j2 + 1], wv.y, t1);
                }
            }
        }
    }

    // epilogue: bilinear weight/index tables, all in registers
    #pragma unroll
    for (int r = 0; r < 2; r++) {
        int h = h0 + r;
        #pragma unroll
        for (int kk = 0; kk < KKc; kk++) {
            float2 oyx = *reinterpret_cast<float2*>(&acc[r][kk]);
            float2 mp  = *reinterpret_cast<float2*>(&acc[r][9 + (kk >> 1)]);
            float mraw = (kk & 1) ? mp.y : mp.x;
            float offy = oyx.x + off_b[2 * kk];
            float offx = oyx.y + off_b[2 * kk + 1];
            float mval = 2.f / (1.f + expf(-(mraw + mod_b[kk])));

            float py = (float)h   - 1.f + (float)(kk / 3) + offy;
            float px = (float)pix - 1.f + (float)(kk % 3) + offx;
            float y0f = floorf(py), x0f = floorf(px);
            float dy = py - y0f, dx = px - x0f;
            int y0 = (int)y0f, x0 = (int)x0f;
            int y1 = y0 + 1,   x1 = x0 + 1;

            float v00 = (y0 >= 0 && y0 < H && x0 >= 0 && x0 < W) ? 1.f : 0.f;
            float v01 = (y0 >= 0 && y0 < H && x1 >= 0 && x1 < W) ? 1.f : 0.f;
            float v10 = (y1 >= 0 && y1 < H && x0 >= 0 && x0 < W) ? 1.f : 0.f;
            float v11 = (y1 >= 0 && y1 < H && x1 >= 0 && x1 < W) ? 1.f : 0.f;

            int y0c = min(max(y0, 0), H - 1), y1c = min(max(y1, 0), H - 1);
            int x0c = min(max(x0, 0), W - 1), x1c = min(max(x1, 0), W - 1);

            float4 wv;
            wv.x = (1.f - dy) * (1.f - dx) * mval * v00;
            wv.y = (1.f - dy) * dx         * mval * v01;
            wv.z = dy         * (1.f - dx) * mval * v10;
            wv.w = dy         * dx         * mval * v11;
            int4 iv;
            iv.x = y0c * W + x0c;  iv.y = y0c * W + x1c;
            iv.z = y1c * W + x0c;  iv.w = y1c * W + x1c;

            size_t t = (((size_t)b * KKc + kk) << 14) + h * W + pix;
            wts[t] = wv;
            idx[t] = iv;
        }
    }
}

// ---------------- deformable im2col via precomputed tables ----------------
__global__ void deform_col_kernel(const float* __restrict__ in,
                                  const float4* __restrict__ wts,
                                  const int4* __restrict__ idx,
                                  float* __restrict__ col) {
    int t = blockIdx.x * blockDim.x + threadIdx.x;   // (b*9+kk)*HW + hw
    if (t >= BB * KKc * HW) return;
    int hw = t & (HW - 1);
    int u  = t >> 14;
    int kk = u % KKc;
    int b  = u / KKc;

    float4 w = wts[t];
    int4  ii = idx[t];

    const float* p = in + (size_t)b * C * HW;
    float* o = col + ((size_t)b * CK + kk) * HW + hw;
    #pragma unroll 4
    for (int c = 0; c < C; c++) {
        float v = p[ii.x] * w.x + p[ii.y] * w.y + p[ii.z] * w.z + p[ii.w] * w.w;
        *o = v;
        p += HW;
        o += (size_t)KKc * HW;
    }
}

// ---------------- main GEMM: 96 x 864 x 16384/batch, f32x2 packed ----------
__global__ void __launch_bounds__(256) sgemm96_kernel(
    const float* __restrict__ A,      // [96][864]
    const float* __restrict__ Bmat,   // [B][864][HW]
    float* __restrict__ Out)          // [B][96][HW]
{
    constexpr int BK = 16, BN = 128, BM = 96;
    __shared__ float As[BK][BM + 1];
    __shared__ float Bs[BK][BN];

    int tid = threadIdx.x;
    int b   = blockIdx.y;
    int n0  = blockIdx.x * BN;
    int tx  = tid & 15;
    int ty  = tid >> 4;

    const float* Bb = Bmat + (size_t)b * CK * HW;

    ull acc2[6][4];
    #pragma unroll
    for (int i = 0; i < 6; i++)
        #pragma unroll
        for (int j = 0; j < 4; j++) acc2[i][j] = 0ull;

    int br = tid >> 5;           // 0..7
    int bc = (tid & 31) * 4;     // 0..124

    for (int k0 = 0; k0 < CK; k0 += BK) {
        #pragma unroll
        for (int i = 0; i < (BM * BK) / 256; i++) {
            int e = tid + i * 256;
            int m = e >> 4;
            int k = e & 15;
            As[k][m] = A[m * CK + k0 + k];
        }
        #pragma unroll
        for (int i = 0; i < 2; i++) {
            float4 v = *reinterpret_cast<const float4*>(
                Bb + (size_t)(k0 + br + 8 * i) * HW + n0 + bc);
            *reinterpret_cast<float4*>(&Bs[br + 8 * i][bc]) = v;
        }
        __syncthreads();

        #pragma unroll
        for (int k = 0; k < BK; k++) {
            ull a2[6];
            #pragma unroll
            for (int i = 0; i < 6; i++) a2[i] = bcast2(As[k][ty * 6 + i]);
            const ull* bp = reinterpret_cast<const ull*>(&Bs[k][tx * 8]);
            ull b0 = bp[0], b1 = bp[1], b2v = bp[2], b3 = bp[3];
            #pragma unroll
            for (int i = 0; i < 6; i++) {
                FMA2(acc2[i][0], a2[i], b0);
                FMA2(acc2[i][1], a2[i], b1);
                FMA2(acc2[i][2], a2[i], b2v);
                FMA2(acc2[i][3], a2[i], b3);
            }
        }
        __syncthreads();
    }

    #pragma unroll
    for (int i = 0; i < 6; i++) {
        int m = ty * 6 + i;
        float* op = Out + ((size_t)b * BM + m) * HW + n0 + tx * 8;
        float2 p0 = *reinterpret_cast<float2*>(&acc2[i][0]);
        float2 p1 = *reinterpret_cast<float2*>(&acc2[i][1]);
        float2 p2 = *reinterpret_cast<float2*>(&acc2[i][2]);
        float2 p3 = *reinterpret_cast<float2*>(&acc2[i][3]);
        *reinterpret_cast<float4*>(op)     = make_float4(p0.x, p0.y, p1.x, p1.y);
        *reinterpret_cast<float4*>(op + 4) = make_float4(p2.x, p2.y, p3.x, p3.y);
    }
}

// ---------------- batch norm ----------------
__global__ void bn_stats_kernel(const float* __restrict__ X,
                                float* __restrict__ stats) {
    int c = blockIdx.x;
    float s = 0.f, s2 = 0.f;
    for (int i = threadIdx.x; i < NPIX; i += blockDim.x) {
        int b  = i >> 14;
        int hw = i & (HW - 1);
        float v = X[((size_t)b * C + c) * HW + hw];
        s  += v;
        s2 += v * v;
    }
    __shared__ float sh[256], sh2[256];
    sh[threadIdx.x] = s; sh2[threadIdx.x] = s2;
    __syncthreads();
    for (int st = 128; st > 0; st >>= 1) {
        if (threadIdx.x < st) {
            sh[threadIdx.x]  += sh[threadIdx.x + st];
            sh2[threadIdx.x] += sh2[threadIdx.x + st];
        }
        __syncthreads();
    }
    if (threadIdx.x == 0) {
        float inv = 1.f / (float)NPIX;
        float mean = sh[0] * inv;
        float var  = sh2[0] * inv - mean * mean;
        stats[c]     = mean;
        stats[C + c] = rsqrtf(var + 1e-5f);
    }
}

__global__ void bn_lrelu_kernel(const float* __restrict__ X,
                                const float* __restrict__ gam,
                                const float* __restrict__ bet,
                                const float* __restrict__ stats,
                                float* __restrict__ O) {
    int idx = blockIdx.x * blockDim.x + threadIdx.x;
    if (idx >= BB * C * HW) return;
    int c = (idx / HW) % C;
    float v = (X[idx] - stats[c]) * stats[C + c] * gam[c] + bet[c];
    O[idx] = v >= 0.f ? v : 0.1f * v;
}

__global__ void bn_add_kernel(const float* __restrict__ Xres,
                              const float* __restrict__ Hc,
                              const float* __restrict__ gam,
                              const float* __restrict__ bet,
                              const float* __restrict__ stats,
                              float* __restrict__ O) {
    int idx = blockIdx.x * blockDim.x + threadIdx.x;
    if (idx >= BB * C * HW) return;
    int c = (idx / HW) % C;
    float v = (Hc[idx] - stats[c]) * stats[C + c] * gam[c] + bet[c];
    O[idx] = Xres[idx] + v;
}

// ---------------- launch ----------------
extern "C" void kernel_launch(void* const* d_in, const int* in_sizes, int n_in,
                              void* d_out, int out_size) {
    const float* x        = (const float*)d_in[0];
    const float* d1_off_w = (const float*)d_in[1];
    const float* d1_off_b = (const float*)d_in[2];
    const float* d1_mod_w = (const float*)d_in[3];
    const float* d1_mod_b = (const float*)d_in[4];
    const float* d1_w     = (const float*)d_in[5];
    const float* d2_off_w = (const float*)d_in[6];
    const float* d2_off_b = (const float*)d_in[7];
    const float* d2_mod_w = (const float*)d_in[8];
    const float* d2_mod_b = (const float*)d_in[9];
    const float* d2_w     = (const float*)d_in[10];
    const float* bn_g     = (const float*)d_in[11];
    const float* bn_b     = (const float*)d_in[12];
    float* out = (float*)d_out;

    float *p_col, *p_conv, *p_act, *p_stats;
    ull* p_wtp; float4* p_wts; int4* p_idx;
    cudaGetSymbolAddress((void**)&p_col,   g_col);
    cudaGetSymbolAddress((void**)&p_wtp,   g_wtp);
    cudaGetSymbolAddress((void**)&p_wts,   g_wts);
    cudaGetSymbolAddress((void**)&p_idx,   g_idx);
    cudaGetSymbolAddress((void**)&p_conv,  g_conv);
    cudaGetSymbolAddress((void**)&p_act,   g_act);
    cudaGetSymbolAddress((void**)&p_stats, g_stats);

    const int NT = 256;
    const int nCol  = BB * KKc * HW;                 // 589824
    const int nElem = BB * C * HW;                   // 6291456
    dim3 gemm_grid(HW / 128, BB);                    // (128, 4)
    dim3 off_grid(H, BB);                            // (128, 4): 64 row-pairs x 2 halves

    // ---------- layer 1 ----------
    wprep_kernel<<<(CK * 14 + NT - 1) / NT, NT>>>(d1_off_w, d1_mod_w, p_wtp);
    offconv_kernel<<<off_grid, 64>>>(p_wtp, x, d1_off_b, d1_mod_b, p_wts, p_idx);
    deform_col_kernel<<<(nCol + NT - 1) / NT, NT>>>(x, p_wts, p_idx, p_col);
    sgemm96_kernel<<<gemm_grid, NT>>>(d1_w, p_col, p_conv);
    bn_stats_kernel<<<C, NT>>>(p_conv, p_stats);
    bn_lrelu_kernel<<<(nElem + NT - 1) / NT, NT>>>(p_conv, bn_g, bn_b, p_stats, p_act);

    // ---------- layer 2 ----------
    wprep_kernel<<<(CK * 14 + NT - 1) / NT, NT>>>(d2_off_w, d2_mod_w, p_wtp);
    offconv_kernel<<<off_grid, 64>>>(p_wtp, p_act, d2_off_b, d2_mod_b, p_wts, p_idx);
    deform_col_kernel<<<(nCol + NT - 1) / NT, NT>>>(p_act, p_wts, p_idx, p_col);
    sgemm96_kernel<<<gemm_grid, NT>>>(d2_w, p_col, p_conv);
    bn_stats_kernel<<<C, NT>>>(p_conv, p_stats);
    bn_add_kernel<<<(nElem + NT - 1) / NT, NT>>>(x, p_conv, bn_g, bn_b, p_stats, out);
}

// round 4
// speedup vs baseline: 1.7379x; 1.3121x over previous
#include <cuda_runtime.h>
#include <math.h>
#include <stdint.h>

#define BB 4
#define C 96
#define H 128
#define W 128
#define HW (H*W)          // 16384
#define KKc 9
#define CK (C*KKc)        // 864
#define NPIX (BB*HW)      // 65536 per channel

typedef unsigned long long ull;

// ---------------- device scratch (no allocations allowed) ----------------
__device__ float  g_col [ (size_t)BB * CK * HW ];   // 226.5 MB deform-col
__device__ ull    g_wtp [ CK * 14 ];                // offset|mask weights, opair-packed
__device__ float4 g_wts [ (size_t)BB * KKc * HW ];  // bilinear weights (mask folded)
__device__ int4   g_idx [ (size_t)BB * KKc * HW ];  // bilinear gather indices
__device__ float  g_conv[ (size_t)BB * C * HW ];    // deform-conv output
__device__ float  g_act [ (size_t)BB * C * HW ];    // post BN+leakyrelu
__device__ float  g_stats[ 2 * C ];                 // mean | rstd

// packed f32x2 FMA (FFMA2) — only reachable via explicit PTX on sm_10x
#define FMA2(d, a, b) \
    asm("fma.rn.f32x2 %0, %1, %2, %0;" : "+l"(d) : "l"(a), "l"(b))

__device__ __forceinline__ ull bcast2(float v) {
    ull r;
    unsigned int u = __float_as_uint(v);
    asm("mov.b64 %0, {%1, %1};" : "=l"(r) : "r"(u));
    return r;
}

// ---------------- weight prep: wtp[ck][j] = (w[2j][ck], w[2j+1][ck]) --------
__global__ void wprep_kernel(const float* __restrict__ offw,
                             const float* __restrict__ modw,
                             ull* __restrict__ wtp) {
    int t = blockIdx.x * blockDim.x + threadIdx.x;   // ck*14 + j
    if (t >= CK * 14) return;
    int ck = t / 14, j = t - ck * 14;
    int o0 = 2 * j, o1 = 2 * j + 1;
    float a = (o0 < 18) ? offw[o0 * CK + ck] : modw[(o0 - 18) * CK + ck];
    float b = 0.f;
    if (o1 < 27)
        b = (o1 < 18) ? offw[o1 * CK + ck] : modw[(o1 - 18) * CK + ck];
    float2 p = make_float2(a, b);
    wtp[t] = *reinterpret_cast<ull*>(&p);
}

// ---------------------------------------------------------------------------
// Direct 3x3 conv producing 27 outputs/pixel + bilinear-table epilogue.
// 256 threads = 4 channel-groups (24 ch each) x 64 pixel-columns x 2 rows.
// Tree-reduced through smem; group 0 runs the epilogue.
// ---------------------------------------------------------------------------
__global__ void __launch_bounds__(256) offconv_kernel(
    const ull* __restrict__ wtp,     // [864][14] packed pairs
    const float* __restrict__ X,     // [B][C][H][W]
    const float* __restrict__ off_b, // [18]
    const float* __restrict__ mod_b, // [9]
    float4* __restrict__ wts,
    int4*  __restrict__ idx)
{
    __shared__ ull red[3][64][28];   // partials from groups 1..3

    int tid  = threadIdx.x;
    int lane = tid & 63;             // pixel column within 64-group
    int grp  = tid >> 6;             // channel group 0..3
    int half = blockIdx.x & 1;
    int h0   = (blockIdx.x >> 1) * 2;
    int b    = blockIdx.y;
    int pix  = half * 64 + lane;

    const float* Xb = X + (size_t)b * C * HW;

    ull acc[2][14];
    #pragma unroll
    for (int r = 0; r < 2; r++)
        #pragma unroll
        for (int j = 0; j < 14; j++) acc[r][j] = 0ull;

    bool xm_ok = (pix > 0);
    bool xp_ok = (pix < W - 1);

    int c0 = grp * 24;
    for (int ci = 0; ci < 24; ci++) {
        int c = c0 + ci;
        ull tb[4][3];
        #pragma unroll
        for (int rr = 0; rr < 4; rr++) {
            int y = h0 - 1 + rr;
            bool yok = (y >= 0) && (y < H);
            const float* row = Xb + (size_t)c * HW + y * W + pix;
            float vm = (yok && xm_ok) ? row[-1] : 0.f;
            float v0 = yok ? row[0] : 0.f;
            float vp = (yok && xp_ok) ? row[1] : 0.f;
            tb[rr][0] = bcast2(vm);
            tb[rr][1] = bcast2(v0);
            tb[rr][2] = bcast2(vp);
        }
        const ulonglong2* wrow =
            reinterpret_cast<const ulonglong2*>(wtp + (size_t)c * 9 * 14);
        #pragma unroll
        for (int ky = 0; ky < 3; ky++) {
            #pragma unroll
            for (int kx = 0; kx < 3; kx++) {
                int tap = ky * 3 + kx;
                ull t0 = tb[ky][kx];
                ull t1 = tb[ky + 1][kx];
                #pragma unroll
                for (int j2 = 0; j2 < 7; j2++) {
                    ulonglong2 wv = wrow[tap * 7 + j2];
                    FMA2(acc[0][2 * j2],     wv.x, t0);
                    FMA2(acc[1][2 * j2],     wv.x, t1);
                    FMA2(acc[0][2 * j2 + 1], wv.y, t0);
                    FMA2(acc[1][2 * j2 + 1], wv.y, t1);
                }
            }
        }
    }

    // tree reduce: groups 1..3 dump partials; group 0 accumulates
    if (grp > 0) {
        #pragma unroll
        for (int r = 0; r < 2; r++)
            #pragma unroll
            for (int j = 0; j < 14; j++)
                red[grp - 1][lane][r * 14 + j] = acc[r][j];
    }
    __syncthreads();
    if (grp != 0) return;

    #pragma unroll
    for (int g = 0; g < 3; g++) {
        #pragma unroll
        for (int r = 0; r < 2; r++) {
            #pragma unroll
            for (int j = 0; j < 14; j++) {
                ull p = red[g][lane][r * 14 + j];
                float2 pa = *reinterpret_cast<float2*>(&acc[r][j]);
                float2 pb = *reinterpret_cast<float2*>(&p);
                pa.x += pb.x; pa.y += pb.y;
                acc[r][j] = *reinterpret_cast<ull*>(&pa);
            }
        }
    }

    // epilogue: bilinear weight/index tables, all in registers
    #pragma unroll
    for (int r = 0; r < 2; r++) {
        int h = h0 + r;
        #pragma unroll
        for (int kk = 0; kk < KKc; kk++) {
            float2 oyx = *reinterpret_cast<float2*>(&acc[r][kk]);
            float2 mp  = *reinterpret_cast<float2*>(&acc[r][9 + (kk >> 1)]);
            float mraw = (kk & 1) ? mp.y : mp.x;
            float offy = oyx.x + off_b[2 * kk];
            float offx = oyx.y + off_b[2 * kk + 1];
            float mval = 2.f / (1.f + expf(-(mraw + mod_b[kk])));

            float py = (float)h   - 1.f + (float)(kk / 3) + offy;
            float px = (float)pix - 1.f + (float)(kk % 3) + offx;
            float y0f = floorf(py), x0f = floorf(px);
            float dy = py - y0f, dx = px - x0f;
            int y0 = (int)y0f, x0 = (int)x0f;
            int y1 = y0 + 1,   x1 = x0 + 1;

            float v00 = (y0 >= 0 && y0 < H && x0 >= 0 && x0 < W) ? 1.f : 0.f;
            float v01 = (y0 >= 0 && y0 < H && x1 >= 0 && x1 < W) ? 1.f : 0.f;
            float v10 = (y1 >= 0 && y1 < H && x0 >= 0 && x0 < W) ? 1.f : 0.f;
            float v11 = (y1 >= 0 && y1 < H && x1 >= 0 && x1 < W) ? 1.f : 0.f;

            int y0c = min(max(y0, 0), H - 1), y1c = min(max(y1, 0), H - 1);
            int x0c = min(max(x0, 0), W - 1), x1c = min(max(x1, 0), W - 1);

            float4 wv;
            wv.x = (1.f - dy) * (1.f - dx) * mval * v00;
            wv.y = (1.f - dy) * dx         * mval * v01;
            wv.z = dy         * (1.f - dx) * mval * v10;
            wv.w = dy         * dx         * mval * v11;
            int4 iv;
            iv.x = y0c * W + x0c;  iv.y = y0c * W + x1c;
            iv.z = y1c * W + x0c;  iv.w = y1c * W + x1c;

            size_t t = (((size_t)b * KKc + kk) << 14) + h * W + pix;
            wts[t] = wv;
            idx[t] = iv;
        }
    }
}

// ---------------- deformable im2col via precomputed tables ----------------
__global__ void deform_col_kernel(const float* __restrict__ in,
                                  const float4* __restrict__ wts,
                                  const int4* __restrict__ idx,
                                  float* __restrict__ col) {
    int t = blockIdx.x * blockDim.x + threadIdx.x;   // (b*9+kk)*HW + hw
    if (t >= BB * KKc * HW) return;
    int hw = t & (HW - 1);
    int u  = t >> 14;
    int kk = u % KKc;
    int b  = u / KKc;

    float4 w = wts[t];
    int4  ii = idx[t];

    const float* p = in + (size_t)b * C * HW;
    float* o = col + ((size_t)b * CK + kk) * HW + hw;
    #pragma unroll 4
    for (int c = 0; c < C; c++) {
        float v = p[ii.x] * w.x + p[ii.y] * w.y + p[ii.z] * w.z + p[ii.w] * w.w;
        *o = v;
        p += HW;
        o += (size_t)KKc * HW;
    }
}

// ---------------- main GEMM: 96 x 864 x 16384/batch, f32x2 packed ----------
// BK=32, vectorized conflict-free LDS, n-tile split in halves.
__global__ void __launch_bounds__(256) sgemm96_kernel(
    const float* __restrict__ A,      // [96][864]
    const float* __restrict__ Bmat,   // [B][864][HW]
    float* __restrict__ Out)          // [B][96][HW]
{
    constexpr int BK = 32, BN = 128, BM = 96;
    __shared__ float As[BK][BM + 2];   // row = 98 floats (8B-aligned rows)
    __shared__ float Bs[BK][BN];

    int tid = threadIdx.x;
    int b   = blockIdx.y;
    int n0  = blockIdx.x * BN;
    int tx  = tid & 15;
    int ty  = tid >> 4;

    const float* Bb = Bmat + (size_t)b * CK * HW;

    ull acc2[6][4];
    #pragma unroll
    for (int i = 0; i < 6; i++)
        #pragma unroll
        for (int j = 0; j < 4; j++) acc2[i][j] = 0ull;

    int br = tid >> 3;           // 0..31  (B row)
    int bq = tid & 7;            // 0..7   (col group)

    for (int k0 = 0; k0 < CK; k0 += BK) {
        // A tile: 96 x 32, float4 gmem loads, scalar transposed stores
        #pragma unroll
        for (int i = 0; i < 3; i++) {
            int e = tid + i * 256;       // 0..767
            int m  = e >> 3;
            int kq = e & 7;
            float4 v = *reinterpret_cast<const float4*>(&A[m * CK + k0 + kq * 4]);
            As[kq * 4 + 0][m] = v.x;
            As[kq * 4 + 1][m] = v.y;
            As[kq * 4 + 2][m] = v.z;
            As[kq * 4 + 3][m] = v.w;
        }
        // B tile: 32 x 128, coalesced float4 (8 threads cover 128B per j)
        #pragma unroll
        for (int j = 0; j < 4; j++) {
            float4 v = *reinterpret_cast<const float4*>(
                Bb + (size_t)(k0 + br) * HW + n0 + bq * 4 + j * 32);
            *reinterpret_cast<float4*>(&Bs[br][bq * 4 + j * 32]) = v;
        }
        __syncthreads();

        #pragma unroll
        for (int k = 0; k < BK; k++) {
            float2 a01 = *reinterpret_cast<const float2*>(&As[k][ty * 6]);
            float2 a23 = *reinterpret_cast<const float2*>(&As[k][ty * 6 + 2]);
            float2 a45 = *reinterpret_cast<const float2*>(&As[k][ty * 6 + 4]);
            ull a2[6];
            a2[0] = bcast2(a01.x); a2[1] = bcast2(a01.y);
            a2[2] = bcast2(a23.x); a2[3] = bcast2(a23.y);
            a2[4] = bcast2(a45.x); a2[5] = bcast2(a45.y);

            float4 bl = *reinterpret_cast<const float4*>(&Bs[k][tx * 4]);
            float4 bh = *reinterpret_cast<const float4*>(&Bs[k][64 + tx * 4]);
            float2 q0 = make_float2(bl.x, bl.y);
            float2 q1 = make_float2(bl.z, bl.w);
            float2 q2 = make_float2(bh.x, bh.y);
            float2 q3 = make_float2(bh.z, bh.w);
            ull b0 = *reinterpret_cast<ull*>(&q0);
            ull b1 = *reinterpret_cast<ull*>(&q1);
            ull b2v = *reinterpret_cast<ull*>(&q2);
            ull b3 = *reinterpret_cast<ull*>(&q3);

            #pragma unroll
            for (int i = 0; i < 6; i++) {
                FMA2(acc2[i][0], a2[i], b0);
                FMA2(acc2[i][1], a2[i], b1);
                FMA2(acc2[i][2], a2[i], b2v);
                FMA2(acc2[i][3], a2[i], b3);
            }
        }
        __syncthreads();
    }

    #pragma unroll
    for (int i = 0; i < 6; i++) {
        int m = ty * 6 + i;
        float* op = Out + ((size_t)b * BM + m) * HW + n0 + tx * 4;
        float2 p0 = *reinterpret_cast<float2*>(&acc2[i][0]);
        float2 p1 = *reinterpret_cast<float2*>(&acc2[i][1]);
        float2 p2 = *reinterpret_cast<float2*>(&acc2[i][2]);
        float2 p3 = *reinterpret_cast<float2*>(&acc2[i][3]);
        *reinterpret_cast<float4*>(op)      = make_float4(p0.x, p0.y, p1.x, p1.y);
        *reinterpret_cast<float4*>(op + 64) = make_float4(p2.x, p2.y, p3.x, p3.y);
    }
}

// ---------------- batch norm ----------------
__global__ void bn_stats_kernel(const float* __restrict__ X,
                                float* __restrict__ stats) {
    int c = blockIdx.x;
    float s = 0.f, s2 = 0.f;
    for (int i = threadIdx.x; i < NPIX; i += blockDim.x) {
        int b  = i >> 14;
        int hw = i & (HW - 1);
        float v = X[((size_t)b * C + c) * HW + hw];
        s  += v;
        s2 += v * v;
    }
    __shared__ float sh[256], sh2[256];
    sh[threadIdx.x] = s; sh2[threadIdx.x] = s2;
    __syncthreads();
    for (int st = 128; st > 0; st >>= 1) {
        if (threadIdx.x < st) {
            sh[threadIdx.x]  += sh[threadIdx.x + st];
            sh2[threadIdx.x] += sh2[threadIdx.x + st];
        }
        __syncthreads();
    }
    if (threadIdx.x == 0) {
        float inv = 1.f / (float)NPIX;
        float mean = sh[0] * inv;
        float var  = sh2[0] * inv - mean * mean;
        stats[c]     = mean;
        stats[C + c] = rsqrtf(var + 1e-5f);
    }
}

__global__ void bn_lrelu_kernel(const float* __restrict__ X,
                                const float* __restrict__ gam,
                                const float* __restrict__ bet,
                                const float* __restrict__ stats,
                                float* __restrict__ O) {
    int idx = blockIdx.x * blockDim.x + threadIdx.x;
    if (idx >= BB * C * HW) return;
    int c = (idx / HW) % C;
    float v = (X[idx] - stats[c]) * stats[C + c] * gam[c] + bet[c];
    O[idx] = v >= 0.f ? v : 0.1f * v;
}

__global__ void bn_add_kernel(const float* __restrict__ Xres,
                              const float* __restrict__ Hc,
                              const float* __restrict__ gam,
                              const float* __restrict__ bet,
                              const float* __restrict__ stats,
                              float* __restrict__ O) {
    int idx = blockIdx.x * blockDim.x + threadIdx.x;
    if (idx >= BB * C * HW) return;
    int c = (idx / HW) % C;
    float v = (Hc[idx] - stats[c]) * stats[C + c] * gam[c] + bet[c];
    O[idx] = Xres[idx] + v;
}

// ---------------- launch ----------------
extern "C" void kernel_launch(void* const* d_in, const int* in_sizes, int n_in,
                              void* d_out, int out_size) {
    const float* x        = (const float*)d_in[0];
    const float* d1_off_w = (const float*)d_in[1];
    const float* d1_off_b = (const float*)d_in[2];
    const float* d1_mod_w = (const float*)d_in[3];
    const float* d1_mod_b = (const float*)d_in[4];
    const float* d1_w     = (const float*)d_in[5];
    const float* d2_off_w = (const float*)d_in[6];
    const float* d2_off_b = (const float*)d_in[7];
    const float* d2_mod_w = (const float*)d_in[8];
    const float* d2_mod_b = (const float*)d_in[9];
    const float* d2_w     = (const float*)d_in[10];
    const float* bn_g     = (const float*)d_in[11];
    const float* bn_b     = (const float*)d_in[12];
    float* out = (float*)d_out;

    float *p_col, *p_conv, *p_act, *p_stats;
    ull* p_wtp; float4* p_wts; int4* p_idx;
    cudaGetSymbolAddress((void**)&p_col,   g_col);
    cudaGetSymbolAddress((void**)&p_wtp,   g_wtp);
    cudaGetSymbolAddress((void**)&p_wts,   g_wts);
    cudaGetSymbolAddress((void**)&p_idx,   g_idx);
    cudaGetSymbolAddress((void**)&p_conv,  g_conv);
    cudaGetSymbolAddress((void**)&p_act,   g_act);
    cudaGetSymbolAddress((void**)&p_stats, g_stats);

    const int NT = 256;
    const int nCol  = BB * KKc * HW;                 // 589824
    const int nElem = BB * C * HW;                   // 6291456
    dim3 gemm_grid(HW / 128, BB);                    // (128, 4)
    dim3 off_grid(H, BB);                            // (128, 4)

    // ---------- layer 1 ----------
    wprep_kernel<<<(CK * 14 + NT - 1) / NT, NT>>>(d1_off_w, d1_mod_w, p_wtp);
    offconv_kernel<<<off_grid, 256>>>(p_wtp, x, d1_off_b, d1_mod_b, p_wts, p_idx);
    deform_col_kernel<<<(nCol + NT - 1) / NT, NT>>>(x, p_wts, p_idx, p_col);
    sgemm96_kernel<<<gemm_grid, NT>>>(d1_w, p_col, p_conv);
    bn_stats_kernel<<<C, NT>>>(p_conv, p_stats);
    bn_lrelu_kernel<<<(nElem + NT - 1) / NT, NT>>>(p_conv, bn_g, bn_b, p_stats, p_act);

    // ---------- layer 2 ----------
    wprep_kernel<<<(CK * 14 + NT - 1) / NT, NT>>>(d2_off_w, d2_mod_w, p_wtp);
    offconv_kernel<<<off_grid, 256>>>(p_wtp, p_act, d2_off_b, d2_mod_b, p_wts, p_idx);
    deform_col_kernel<<<(nCol + NT - 1) / NT, NT>>>(p_act, p_wts, p_idx, p_col);
    sgemm96_kernel<<<gemm_grid, NT>>>(d2_w, p_col, p_conv);
    bn_stats_kernel<<<C, NT>>>(p_conv, p_stats);
    bn_add_kernel<<<(nElem + NT - 1) / NT, NT>>>(x, p_conv, bn_g, bn_b, p_stats, out);
}